// round 12
// baseline (speedup 1.0000x reference)
#include <cuda_runtime.h>

#define N_ 20000
#define E_ 100000
#define KF 8
#define FIN 1024
#define FOUT 512
#define KTOT 1120
#define MS 32768

// ---------------- device scratch (no allocations) ----------------
__device__ float               g_f[KF * N_];
__device__ int                 g_hk[KF * N_];
__device__ unsigned long long  g_feA[KF * E_];
__device__ unsigned long long  g_feB[KF * E_];
__device__ unsigned long long  g_mk[KF * MS];
__device__ float               g_D[KF * N_];
__device__ float               g_coord[(size_t)N_ * 96];

// ---------------- packed f32x2 helpers ----------------
#define FMA2(d, a, b) asm("fma.rn.f32x2 %0, %1, %2, %0;" : "+l"(d) : "l"(a), "l"(b))
#define PK2(d, x, y)  asm("mov.b64 %0, {%1, %2};" : "=l"(d) : "f"(x), "f"(y))
#define UPK2(x, y, d) asm("mov.b64 {%0, %1}, %2;" : "=f"(x), "=f"(y) : "l"(d))

// path-compressing find on shared u16 parents (racy writes are valid roots -> safe)
__device__ __forceinline__ int sfind(unsigned short* spar, int x) {
    int r = x;
    while (spar[r] != r) r = spar[r];
    while (spar[x] != r) { int nx = spar[x]; spar[x] = (unsigned short)r; x = nx; }
    return r;
}

// ---------------- f_all ----------------
__global__ __launch_bounds__(256) void k_fall(const float* __restrict__ x,
                                              const float* __restrict__ fw,
                                              const float* __restrict__ fb) {
    __shared__ float ws[KF][FIN];
    int tid = threadIdx.x;
    for (int i = tid; i < KF * FIN; i += 256) ws[i >> 10][i & 1023] = fw[i];
    __syncthreads();
    int warp = tid >> 5, lane = tid & 31;
    int row = blockIdx.x * 8 + warp;
    if (row >= N_) return;
    const float4* xr = (const float4*)(x + (size_t)row * FIN);
    float acc[KF];
#pragma unroll
    for (int k = 0; k < KF; k++) acc[k] = 0.f;
    for (int i = lane; i < FIN / 4; i += 32) {
        float4 xv = xr[i];
        int c = i * 4;
#pragma unroll
        for (int k = 0; k < KF; k++)
            acc[k] += xv.x * ws[k][c] + xv.y * ws[k][c + 1] +
                      xv.z * ws[k][c + 2] + xv.w * ws[k][c + 3];
    }
#pragma unroll
    for (int k = 0; k < KF; k++)
#pragma unroll
        for (int o = 16; o; o >>= 1) acc[k] += __shfl_xor_sync(0xFFFFFFFFu, acc[k], o);
    if (lane == 0) {
#pragma unroll
        for (int k = 0; k < KF; k++) g_f[k * N_ + row] = acc[k] + fb[k];
    }
}

// ---------------- fused topology kernel: Boruvka + sort + elder-rule UF ----------------
// One block per filtration (8 blocks total -> 140 SMs stay free for the x-GEMM).
// Dynamic smem (200000 B):
//   phase B: best u64[N_] @0 (160000), spar u16[N_] @160000 (40000)
//   phase U: sf  f32[N_] @0 (80000),  spar2 u16[N_] @80000 (40000)
__global__ __launch_bounds__(1024) void k_topo(const int* __restrict__ ei) {
    extern __shared__ char dyn[];
    unsigned long long* best = (unsigned long long*)dyn;
    unsigned short* spar = (unsigned short*)(dyn + 160000);
    __shared__ int s_fcnt, s_nf, s_mc;
    int k = blockIdx.x, tid = threadIdx.x, lane = tid & 31;
    int kb = k * N_;
    const float* f = g_f + (size_t)kb;
    unsigned long long* mk = g_mk + (size_t)k * MS;
    unsigned long long* feA = g_feA + (size_t)k * E_;
    unsigned long long* feB = g_feB + (size_t)k * E_;
    int* hk = g_hk + kb;

    // ---- init ----
    for (int i = tid; i < N_; i += 1024) { best[i] = ~0ull; spar[i] = (unsigned short)i; }
    for (int i = tid; i < MS; i += 1024) mk[i] = ~0ull;
    if (tid == 0) { s_fcnt = 0; s_nf = 0; s_mc = 0; }
    __syncthreads();

    // ---- Boruvka rounds (all in-block) ----
    unsigned long long *src = feA, *dst = feB;
    for (int round = 0; ; round++) {
        int lim = (round == 0) ? E_ : s_fcnt;
        if (lim == 0) break;
        int iters = (lim + 1023) >> 10;
        // scan: best-edge atomics (shared) + frontier compaction
        for (int it = 0; it < iters; it++) {
            int j = tid + (it << 10);
            bool keep = false;
            unsigned long long kv = 0;
            if (j < lim) {
                int e, u, v;
                if (round == 0) {
                    e = j; u = ei[e]; v = ei[E_ + e];
                    float key = fmaxf(f[u], f[v]);
                    unsigned b = __float_as_uint(key);
                    b = (b & 0x80000000u) ? ~b : (b | 0x80000000u);
                    kv = ((unsigned long long)b << 32) | (unsigned)e;
                } else {
                    kv = src[j];
                    e = (int)(unsigned)kv; u = ei[e]; v = ei[E_ + e];
                }
                int cu = sfind(spar, u), cv = sfind(spar, v);
                if (cu != cv) {
                    atomicMin(&best[cu], kv);
                    atomicMin(&best[cv], kv);
                    keep = true;
                }
            }
            unsigned mb = __ballot_sync(0xFFFFFFFFu, keep);
            if (mb) {
                int leader = __ffs(mb) - 1;
                int pos = 0;
                if (lane == leader) pos = atomicAdd(&s_nf, __popc(mb));
                pos = __shfl_sync(0xFFFFFFFFu, pos, leader);
                if (keep) dst[pos + __popc(mb & ((1u << lane) - 1))] = kv;
            }
        }
        __syncthreads();
        // hook: roots pick best edge, emit MSF edge (dedup reciprocal pairs)
        for (int n = tid; n < N_; n += 1024) {
            bool emit = false;
            unsigned long long bb = 0;
            if (spar[n] == (unsigned short)n) {
                bb = best[n];
                if (bb != ~0ull) {
                    unsigned e = (unsigned)bb;
                    int cu = sfind(spar, ei[e]);
                    int cv = sfind(spar, ei[E_ + e]);
                    int o = (cu == n) ? cv : cu;
                    hk[n] = o;
                    emit = (best[o] != bb) || (n < o);
                } else hk[n] = -1;
            }
            unsigned mb = __ballot_sync(0xFFFFFFFFu, emit);
            if (mb) {
                int leader = __ffs(mb) - 1;
                int pos = 0;
                if (lane == leader) pos = atomicAdd(&s_mc, __popc(mb));
                pos = __shfl_sync(0xFFFFFFFFu, pos, leader);
                if (emit) mk[pos + __popc(mb & ((1u << lane) - 1))] = bb;
            }
        }
        __syncthreads();
        // contract: follow hook chains to 2-cycle terminus (min id), reset best
        for (int n = tid; n < N_; n += 1024) {
            if (spar[n] == (unsigned short)n && best[n] != ~0ull) {
                int x = n;
                for (;;) {
                    int o = hk[x];
                    if (hk[o] == x && x < o) break;
                    x = o;
                }
                spar[n] = (unsigned short)x;
                best[n] = ~0ull;
            }
        }
        __syncthreads();
        if (tid == 0) { s_fcnt = s_nf; s_nf = 0; }
        { unsigned long long* t = src; src = dst; dst = t; }
        __syncthreads();
    }

    // ---- bitonic sort of mk[0..MS) (ascending; padding ~0 sinks to end) ----
    __syncthreads();
    for (unsigned k2 = 2; k2 <= MS; k2 <<= 1) {
        for (unsigned j = k2 >> 1; j > 0; j >>= 1) {
            for (int t = tid; t < MS / 2; t += 1024) {
                unsigned i = 2 * (unsigned)t - ((unsigned)t & (j - 1));
                unsigned long long a = mk[i], b = mk[i + j];
                bool up = ((i & k2) == 0);
                if (up ? (a > b) : (a < b)) { mk[i] = b; mk[i + j] = a; }
            }
            __syncthreads();
        }
    }

    // ---- elder-rule UF (R10 warp-synchronous register-mirrored commit) ----
    float* sf = (float*)dyn;                              // overlay (best dead)
    unsigned short* sp2 = (unsigned short*)(dyn + 80000); // overlay (old spar dead)
    float* D = g_D + (size_t)kb;
    int m = s_mc;
    __syncthreads();
    for (int i = tid; i < N_; i += 1024) {
        float v = f[i];
        sf[i] = v; D[i] = v;
        sp2[i] = (unsigned short)i;
    }
    __syncthreads();
    if (tid < 32) {
        for (int base = 0; base < m; base += 32) {
            int i = base + lane;
            bool valid = (i < m);
            int ru = -1, rv = -2;
            float fu = 0.f, fv = 0.f, kf = 0.f;
            if (valid) {
                unsigned long long kv = mk[i];
                unsigned e = (unsigned)kv;
                unsigned ob = (unsigned)(kv >> 32);
                unsigned fb2 = (ob & 0x80000000u) ? (ob & 0x7FFFFFFFu) : ~ob;
                kf = __uint_as_float(fb2);
                int u = ei[e], v = ei[E_ + e];
                int x = u;                 // path-halving find
                for (;;) { int p = sp2[x]; if (p == x) break; int g2 = sp2[p]; sp2[x] = (unsigned short)g2; x = g2; }
                ru = x; fu = sf[x];
                x = v;
                for (;;) { int p = sp2[x]; if (p == x) break; int g2 = sp2[p]; sp2[x] = (unsigned short)g2; x = g2; }
                rv = x; fv = sf[x];
            }
            __syncwarp();
            int lim2 = min(32, m - base);
            for (int t = 0; t < lim2; t++) {
                int   bru = __shfl_sync(0xFFFFFFFFu, ru, t);
                int   brv = __shfl_sync(0xFFFFFFFFu, rv, t);
                float bfu = __shfl_sync(0xFFFFFFFFu, fu, t);
                float bfv = __shfl_sync(0xFFFFFFFFu, fv, t);
                float bkf = __shfl_sync(0xFFFFFFFFu, kf, t);
                if (bru != brv) {
                    int older   = (bfu <= bfv) ? bru : brv;
                    int younger = bru + brv - older;
                    float folder = (bfu <= bfv) ? bfu : bfv;
                    if (lane == (t & 31)) {
                        sp2[younger] = (unsigned short)older;
                        D[younger] = bkf;
                    }
                    if (ru == younger) { ru = older; fu = folder; }
                    if (rv == younger) { rv = older; fv = folder; }
                }
            }
            __syncwarp();
        }
    }
}

// ---------------- coordinate activations ----------------
__global__ void k_act(const float* __restrict__ tri_t, const float* __restrict__ mu,
                      const float* __restrict__ sig, const float* __restrict__ lw,
                      const float* __restrict__ rc, const float* __restrict__ rr) {
    int i = blockIdx.x * blockDim.x + threadIdx.x;
    if (i >= N_ * KF) return;
    int v = i / KF, k = i - v * KF;
    float b = g_f[k * N_ + v], d = g_D[k * N_ + v];
    float s = sig[0];
    float inv = 1.f / (2.f * s * s);
    float r = fabsf(rr[0]);
    float o[12];
#pragma unroll
    for (int j = 0; j < 3; j++) o[j] = fmaxf(0.f, d - fabsf(tri_t[j] - b));
#pragma unroll
    for (int j = 0; j < 3; j++) {
        float dx = b - mu[2 * j], dy = d - mu[2 * j + 1];
        o[3 + j] = expf(-(dx * dx + dy * dy) * inv);
    }
#pragma unroll
    for (int j = 0; j < 3; j++) o[6 + j] = b * lw[2 * j] + d * lw[2 * j + 1];
#pragma unroll
    for (int j = 0; j < 3; j++) {
        float q = fabsf(b - rc[2 * j]) + fabsf(d - rc[2 * j + 1]);
        o[9 + j] = 1.f / (1.f + q) - 1.f / (1.f + fabsf(r - q));
    }
    float* dst = g_coord + (size_t)v * 96 + k * 12;
#pragma unroll
    for (int j = 0; j < 12; j++) dst[j] = o[j];
}

// ---------------- GEMM part 1: out = x @ Wx^T + bias (independent of topology) ----------------
__global__ __launch_bounds__(256, 2) void k_gemm_x(const float* __restrict__ x,
                                                   const float* __restrict__ W,
                                                   const float* __restrict__ bias,
                                                   float* __restrict__ out) {
    __shared__ float As[16][136];
    __shared__ float Ws[16][136];
    int tid = threadIdx.x;
    int tx = tid & 15, ty = tid >> 4;
    int row0 = blockIdx.x * 128;
    int col0 = blockIdx.y * 128;
    unsigned long long acc[4][8];
#pragma unroll
    for (int p2 = 0; p2 < 4; p2++)
#pragma unroll
        for (int j = 0; j < 8; j++) acc[p2][j] = 0ull;

    for (int kt = 0; kt < 64; kt++) {
        int k0 = kt * 16;
#pragma unroll
        for (int l = 0; l < 2; l++) {
            int idx = tid + l * 256;
            int r = idx >> 2, c4 = idx & 3;
            int grow = row0 + r;
            float4 vv = make_float4(0.f, 0.f, 0.f, 0.f);
            if (grow < N_) vv = *(const float4*)(x + (size_t)grow * FIN + (k0 + c4 * 4));
            As[c4 * 4 + 0][r] = vv.x; As[c4 * 4 + 1][r] = vv.y;
            As[c4 * 4 + 2][r] = vv.z; As[c4 * 4 + 3][r] = vv.w;
        }
#pragma unroll
        for (int l = 0; l < 2; l++) {
            int idx = tid + l * 256;
            int r = idx >> 2, c4 = idx & 3;
            float4 vv = *(const float4*)(W + (size_t)(col0 + r) * KTOT + (k0 + c4 * 4));
            Ws[c4 * 4 + 0][r] = vv.x; Ws[c4 * 4 + 1][r] = vv.y;
            Ws[c4 * 4 + 2][r] = vv.z; Ws[c4 * 4 + 3][r] = vv.w;
        }
        __syncthreads();
#pragma unroll
        for (int kk = 0; kk < 16; kk++) {
            const unsigned long long* a8 = (const unsigned long long*)(&As[kk][ty * 8]);
            unsigned long long ap0 = a8[0], ap1 = a8[1], ap2 = a8[2], ap3 = a8[3];
            float4 w0 = *(const float4*)&Ws[kk][tx * 8];
            float4 w1 = *(const float4*)&Ws[kk][tx * 8 + 4];
            unsigned long long wp[8];
            PK2(wp[0], w0.x, w0.x); PK2(wp[1], w0.y, w0.y);
            PK2(wp[2], w0.z, w0.z); PK2(wp[3], w0.w, w0.w);
            PK2(wp[4], w1.x, w1.x); PK2(wp[5], w1.y, w1.y);
            PK2(wp[6], w1.z, w1.z); PK2(wp[7], w1.w, w1.w);
#pragma unroll
            for (int j = 0; j < 8; j++) {
                FMA2(acc[0][j], ap0, wp[j]);
                FMA2(acc[1][j], ap1, wp[j]);
                FMA2(acc[2][j], ap2, wp[j]);
                FMA2(acc[3][j], ap3, wp[j]);
            }
        }
        __syncthreads();
    }

    float bs[8];
#pragma unroll
    for (int j = 0; j < 8; j++) bs[j] = bias[col0 + tx * 8 + j];
#pragma unroll
    for (int p2 = 0; p2 < 4; p2++) {
        float lo[8], hi[8];
#pragma unroll
        for (int j = 0; j < 8; j++) { UPK2(lo[j], hi[j], acc[p2][j]); }
        int r0 = row0 + ty * 8 + p2 * 2;
        if (r0 < N_) {
            float* o0 = out + (size_t)r0 * FOUT + col0 + tx * 8;
            *(float4*)o0 = make_float4(lo[0] + bs[0], lo[1] + bs[1], lo[2] + bs[2], lo[3] + bs[3]);
            *(float4*)(o0 + 4) = make_float4(lo[4] + bs[4], lo[5] + bs[5], lo[6] + bs[6], lo[7] + bs[7]);
        }
        if (r0 + 1 < N_) {
            float* o1 = out + (size_t)(r0 + 1) * FOUT + col0 + tx * 8;
            *(float4*)o1 = make_float4(hi[0] + bs[0], hi[1] + bs[1], hi[2] + bs[2], hi[3] + bs[3]);
            *(float4*)(o1 + 4) = make_float4(hi[4] + bs[4], hi[5] + bs[5], hi[6] + bs[6], hi[7] + bs[7]);
        }
    }
}

// ---------------- GEMM part 2: out += coord @ Wc^T ----------------
__global__ __launch_bounds__(256, 2) void k_gemm_c(const float* __restrict__ W,
                                                   float* __restrict__ out) {
    __shared__ float As[16][136];
    __shared__ float Ws[16][136];
    int tid = threadIdx.x;
    int tx = tid & 15, ty = tid >> 4;
    int row0 = blockIdx.x * 128;
    int col0 = blockIdx.y * 128;
    unsigned long long acc[4][8];
#pragma unroll
    for (int p2 = 0; p2 < 4; p2++)
#pragma unroll
        for (int j = 0; j < 8; j++) acc[p2][j] = 0ull;

    for (int kt = 0; kt < 6; kt++) {
        int k0 = kt * 16;
#pragma unroll
        for (int l = 0; l < 2; l++) {
            int idx = tid + l * 256;
            int r = idx >> 2, c4 = idx & 3;
            int grow = row0 + r;
            float4 vv = make_float4(0.f, 0.f, 0.f, 0.f);
            if (grow < N_) vv = *(const float4*)(g_coord + (size_t)grow * 96 + (k0 + c4 * 4));
            As[c4 * 4 + 0][r] = vv.x; As[c4 * 4 + 1][r] = vv.y;
            As[c4 * 4 + 2][r] = vv.z; As[c4 * 4 + 3][r] = vv.w;
        }
#pragma unroll
        for (int l = 0; l < 2; l++) {
            int idx = tid + l * 256;
            int r = idx >> 2, c4 = idx & 3;
            float4 vv = *(const float4*)(W + (size_t)(col0 + r) * KTOT + (1024 + k0 + c4 * 4));
            Ws[c4 * 4 + 0][r] = vv.x; Ws[c4 * 4 + 1][r] = vv.y;
            Ws[c4 * 4 + 2][r] = vv.z; Ws[c4 * 4 + 3][r] = vv.w;
        }
        __syncthreads();
#pragma unroll
        for (int kk = 0; kk < 16; kk++) {
            const unsigned long long* a8 = (const unsigned long long*)(&As[kk][ty * 8]);
            unsigned long long ap0 = a8[0], ap1 = a8[1], ap2 = a8[2], ap3 = a8[3];
            float4 w0 = *(const float4*)&Ws[kk][tx * 8];
            float4 w1 = *(const float4*)&Ws[kk][tx * 8 + 4];
            unsigned long long wp[8];
            PK2(wp[0], w0.x, w0.x); PK2(wp[1], w0.y, w0.y);
            PK2(wp[2], w0.z, w0.z); PK2(wp[3], w0.w, w0.w);
            PK2(wp[4], w1.x, w1.x); PK2(wp[5], w1.y, w1.y);
            PK2(wp[6], w1.z, w1.z); PK2(wp[7], w1.w, w1.w);
#pragma unroll
            for (int j = 0; j < 8; j++) {
                FMA2(acc[0][j], ap0, wp[j]);
                FMA2(acc[1][j], ap1, wp[j]);
                FMA2(acc[2][j], ap2, wp[j]);
                FMA2(acc[3][j], ap3, wp[j]);
            }
        }
        __syncthreads();
    }

#pragma unroll
    for (int p2 = 0; p2 < 4; p2++) {
        float lo[8], hi[8];
#pragma unroll
        for (int j = 0; j < 8; j++) { UPK2(lo[j], hi[j], acc[p2][j]); }
        int r0 = row0 + ty * 8 + p2 * 2;
        if (r0 < N_) {
            float* o0 = out + (size_t)r0 * FOUT + col0 + tx * 8;
            float4 a0 = *(float4*)o0, a1 = *(float4*)(o0 + 4);
            a0.x += lo[0]; a0.y += lo[1]; a0.z += lo[2]; a0.w += lo[3];
            a1.x += lo[4]; a1.y += lo[5]; a1.z += lo[6]; a1.w += lo[7];
            *(float4*)o0 = a0; *(float4*)(o0 + 4) = a1;
        }
        if (r0 + 1 < N_) {
            float* o1 = out + (size_t)(r0 + 1) * FOUT + col0 + tx * 8;
            float4 a0 = *(float4*)o1, a1 = *(float4*)(o1 + 4);
            a0.x += hi[0]; a0.y += hi[1]; a0.z += hi[2]; a0.w += hi[3];
            a1.x += hi[4]; a1.y += hi[5]; a1.z += hi[6]; a1.w += hi[7];
            *(float4*)o1 = a0; *(float4*)(o1 + 4) = a1;
        }
    }
}

// ---------------- launcher: x-GEMM forked; 8-block topo kernel leaves it 140 SMs ----------------
extern "C" void kernel_launch(void* const* d_in, const int* in_sizes, int n_in,
                              void* d_out, int out_size) {
    const float* x   = (const float*)d_in[0];
    const int*   ei  = (const int*)d_in[1];
    const float* fw  = (const float*)d_in[2];
    const float* fb  = (const float*)d_in[3];
    const float* tri = (const float*)d_in[4];
    const float* mu  = (const float*)d_in[5];
    const float* sig = (const float*)d_in[6];
    const float* lw  = (const float*)d_in[7];
    const float* rc  = (const float*)d_in[8];
    const float* rr  = (const float*)d_in[9];
    const float* W   = (const float*)d_in[10];
    const float* ob  = (const float*)d_in[11];
    float* out = (float*)d_out;

    cudaStream_t s2;
    cudaStreamCreateWithFlags(&s2, cudaStreamNonBlocking);
    cudaEvent_t evRoot, evX;
    cudaEventCreateWithFlags(&evRoot, cudaEventDisableTiming);
    cudaEventCreateWithFlags(&evX, cudaEventDisableTiming);

    dim3 gg((N_ + 127) / 128, FOUT / 128);

    // fork: x-GEMM runs concurrently with the whole topology pipeline
    cudaEventRecord(evRoot, 0);
    cudaStreamWaitEvent(s2, evRoot, 0);
    k_gemm_x<<<gg, 256, 0, s2>>>(x, W, ob, out);
    cudaEventRecord(evX, s2);

    // topology pipeline on the default stream (8 blocks -> chip mostly free)
    k_fall<<<(N_ + 7) / 8, 256>>>(x, fw, fb);
    cudaFuncSetAttribute(k_topo, cudaFuncAttributeMaxDynamicSharedMemorySize, 200704);
    k_topo<<<KF, 1024, 200704>>>(ei);
    k_act<<<(N_ * KF + 255) / 256, 256>>>(tri, mu, sig, lw, rc, rr);

    // join: coord-GEMM needs both k_act (coord) and k_gemm_x (out initialized)
    cudaStreamWaitEvent(0, evX, 0);
    k_gemm_c<<<gg, 256>>>(W, out);
}

// round 13
// speedup vs baseline: 1.2939x; 1.2939x over previous
#include <cuda_runtime.h>

#define N_ 20000
#define E_ 100000
#define KF 8
#define FIN 1024
#define FOUT 512
#define KTOT 1120
#define MS 32768

// ---------------- device scratch (no allocations) ----------------
__device__ float               g_f[KF * N_];
__device__ int                 g_par[KF * N_];
__device__ int                 g_hk[KF * N_];
__device__ unsigned long long  g_best[KF * N_];
__device__ unsigned long long  g_feA[KF * E_];
__device__ unsigned long long  g_feB[KF * E_];
__device__ int                 g_fcnt[2][KF];
__device__ unsigned long long  g_mk[KF * MS];
__device__ int                 g_mcnt[KF];
__device__ float               g_D[KF * N_];
__device__ float               g_coord[(size_t)N_ * 96];

// ---------------- packed f32x2 helpers ----------------
#define FMA2(d, a, b) asm("fma.rn.f32x2 %0, %1, %2, %0;" : "+l"(d) : "l"(a), "l"(b))
#define PK2(d, x, y)  asm("mov.b64 %0, {%1, %2};" : "=l"(d) : "f"(x), "f"(y))
#define UPK2(x, y, d) asm("mov.b64 {%0, %1}, %2;" : "=f"(x), "=f"(y) : "l"(d))

// ---------------- init ----------------
__global__ void k_init() {
    int i = blockIdx.x * blockDim.x + threadIdx.x;
    if (i < KF * N_) { g_par[i] = i % N_; g_best[i] = ~0ull; }
    if (i < KF * MS) g_mk[i] = ~0ull;
    if (i < KF)      { g_mcnt[i] = 0; g_fcnt[0][i] = 0; g_fcnt[1][i] = 0; }
}

// ---------------- f_all ----------------
__global__ __launch_bounds__(256) void k_fall(const float* __restrict__ x,
                                              const float* __restrict__ fw,
                                              const float* __restrict__ fb) {
    __shared__ float ws[KF][FIN];
    int tid = threadIdx.x;
    for (int i = tid; i < KF * FIN; i += 256) ws[i >> 10][i & 1023] = fw[i];
    __syncthreads();
    int warp = tid >> 5, lane = tid & 31;
    int row = blockIdx.x * 8 + warp;
    if (row >= N_) return;
    const float4* xr = (const float4*)(x + (size_t)row * FIN);
    float acc[KF];
#pragma unroll
    for (int k = 0; k < KF; k++) acc[k] = 0.f;
    for (int i = lane; i < FIN / 4; i += 32) {
        float4 xv = xr[i];
        int c = i * 4;
#pragma unroll
        for (int k = 0; k < KF; k++)
            acc[k] += xv.x * ws[k][c] + xv.y * ws[k][c + 1] +
                      xv.z * ws[k][c + 2] + xv.w * ws[k][c + 3];
    }
#pragma unroll
    for (int k = 0; k < KF; k++)
#pragma unroll
        for (int o = 16; o; o >>= 1) acc[k] += __shfl_xor_sync(0xFFFFFFFFu, acc[k], o);
    if (lane == 0) {
#pragma unroll
        for (int k = 0; k < KF; k++) g_f[k * N_ + row] = acc[k] + fb[k];
    }
}

// ---------------- Boruvka A: round0 computes keys inline; best atomics + compaction ----------------
__global__ void kA_edge(const int* __restrict__ ei, int r) {
    int p = r & 1;
    int i = blockIdx.x * blockDim.x + threadIdx.x;
    int k = i / E_, j = i - k * E_;
    int lane = threadIdx.x & 31;
    bool keep = false;
    unsigned long long kv = 0;
    int lim = (r == 0) ? E_ : g_fcnt[p][k];
    if (j < lim) {
        int e, u, v;
        if (r == 0) {
            e = j; u = ei[e]; v = ei[E_ + e];
            float key = fmaxf(g_f[k * N_ + u], g_f[k * N_ + v]);
            unsigned b = __float_as_uint(key);
            b = (b & 0x80000000u) ? ~b : (b | 0x80000000u);
            kv = ((unsigned long long)b << 32) | (unsigned)e;
        } else {
            kv = p ? g_feB[i] : g_feA[i];
            e = (int)(unsigned)kv; u = ei[e]; v = ei[E_ + e];
        }
        int cu = g_par[k * N_ + u], cv = g_par[k * N_ + v];
        if (cu != cv) {
            atomicMin(&g_best[k * N_ + cu], kv);
            atomicMin(&g_best[k * N_ + cv], kv);
            keep = true;
        }
    }
    unsigned m = __ballot_sync(0xFFFFFFFFu, keep);
    if (!m) return;
    int leader = __ffs(m) - 1;
    int pos = 0;
    if (lane == leader) pos = atomicAdd(&g_fcnt[p ^ 1][k], __popc(m));
    pos = __shfl_sync(0xFFFFFFFFu, pos, leader);
    if (keep) {
        int my = pos + __popc(m & ((1u << lane) - 1));
        if (p) g_feA[k * E_ + my] = kv; else g_feB[k * E_ + my] = kv;
    }
}

// ---------------- Boruvka B: hook + warp-aggregated MSF append (dead-round exit) ----------------
__global__ void kB_hook(const int* __restrict__ ei, int r) {
    int i = blockIdx.x * blockDim.x + threadIdx.x;
    int k = i / N_, n = i - k * N_;
    if (r > 0 && g_fcnt[r & 1][k] == 0) return;
    int lane = threadIdx.x & 31;
    bool emit = false;
    unsigned long long bb = 0;
    if (g_par[i] == n) {
        bb = g_best[i];
        if (bb == ~0ull) {
            g_hk[i] = -1;
        } else {
            unsigned e = (unsigned)bb;
            int u = ei[e], v = ei[E_ + e];
            int cu = g_par[k * N_ + u], cv = g_par[k * N_ + v];
            int o = (cu == n) ? cv : cu;
            g_hk[i] = o;
            unsigned long long bb2 = g_best[k * N_ + o];
            bool recip = (bb2 == bb);
            emit = (!recip || n < o);
        }
    }
    unsigned m = __ballot_sync(0xFFFFFFFFu, emit);
    if (!m) return;
    int leader = __ffs(m) - 1;
    int pos = 0;
    if (lane == leader) pos = atomicAdd(&g_mcnt[k], __popc(m));
    pos = __shfl_sync(0xFFFFFFFFu, pos, leader);
    if (emit) {
        int my = pos + __popc(m & ((1u << lane) - 1));
        g_mk[(size_t)k * MS + my] = bb;
    }
}

// ---------------- Boruvka C: apply hooks + flatten + reset (dead-round exit) ----------------
__global__ void kC_flat(int r) {
    int p = r & 1;
    int i = blockIdx.x * blockDim.x + threadIdx.x;
    if (i >= KF * N_) return;
    int k = i / N_, n = i - k * N_;
    if (r > 0 && g_fcnt[p][k] == 0) return;
    int kb = k * N_;
    int x = n;
    for (;;) {
        int pp = g_par[kb + x];
        if (pp != x) { x = pp; continue; }
        int o = g_hk[kb + x];
        if (o < 0) break;
        if (g_hk[kb + o] == x && x < o) break;
        x = o;
    }
    g_par[i] = x;
    g_best[i] = ~0ull;
    if (n == 0) g_fcnt[p][k] = 0;
}

// ---------------- bitonic sort ----------------
__global__ __launch_bounds__(1024) void k_sloc() {
    __shared__ unsigned long long s[2048];
    unsigned blk = blockIdx.x;
    size_t base = (size_t)blk * 2048;
    unsigned lbase = (blk % (MS / 2048)) * 2048;
    s[threadIdx.x] = g_mk[base + threadIdx.x];
    s[threadIdx.x + 1024] = g_mk[base + threadIdx.x + 1024];
    __syncthreads();
    for (unsigned k2 = 2; k2 <= 2048; k2 <<= 1) {
        for (unsigned j = k2 >> 1; j > 0; j >>= 1) {
            unsigned t = threadIdx.x;
            unsigned i = 2 * t - (t & (j - 1));
            bool up = (((lbase + i) & k2) == 0);
            unsigned long long a = s[i], b = s[i + j];
            if (up ? (a > b) : (a < b)) { s[i] = b; s[i + j] = a; }
            __syncthreads();
        }
    }
    g_mk[base + threadIdx.x] = s[threadIdx.x];
    g_mk[base + threadIdx.x + 1024] = s[threadIdx.x + 1024];
}

__global__ void k_sglob(unsigned K2, unsigned j) {
    unsigned gid = blockIdx.x * blockDim.x + threadIdx.x;
    if (gid >= KF * (MS / 2)) return;
    unsigned filt = gid / (MS / 2), t = gid % (MS / 2);
    unsigned i = 2 * t - (t & (j - 1));
    unsigned l = i + j;
    unsigned long long* g = g_mk + (size_t)filt * MS;
    bool up = ((i & K2) == 0);
    unsigned long long a = g[i], b = g[l];
    if (up ? (a > b) : (a < b)) { g[i] = b; g[l] = a; }
}

__global__ __launch_bounds__(1024) void k_smerge(unsigned K2) {
    __shared__ unsigned long long s[2048];
    unsigned blk = blockIdx.x;
    size_t base = (size_t)blk * 2048;
    unsigned lbase = (blk % (MS / 2048)) * 2048;
    s[threadIdx.x] = g_mk[base + threadIdx.x];
    s[threadIdx.x + 1024] = g_mk[base + threadIdx.x + 1024];
    __syncthreads();
    for (unsigned j = 1024; j > 0; j >>= 1) {
        unsigned t = threadIdx.x;
        unsigned i = 2 * t - (t & (j - 1));
        bool up = (((lbase + i) & K2) == 0);
        unsigned long long a = s[i], b = s[i + j];
        if (up ? (a > b) : (a < b)) { s[i] = b; s[i + j] = a; }
        __syncthreads();
    }
    g_mk[base + threadIdx.x] = s[threadIdx.x];
    g_mk[base + threadIdx.x + 1024] = s[threadIdx.x + 1024];
}

// ---------------- elder-rule UF: warp-synchronous register-mirrored commit (R10 winner) ----------------
__global__ __launch_bounds__(32) void k_uf(const int* __restrict__ ei) {
    extern __shared__ char dyn[];
    float* sf = (float*)dyn;
    unsigned short* spar = (unsigned short*)(dyn + 80000);
    int k = blockIdx.x, lane = threadIdx.x;
    const float* f = g_f + (size_t)k * N_;
    float* D = g_D + (size_t)k * N_;
    {
        const float4* f4 = (const float4*)f;
        float4* D4 = (float4*)D;
        float4* sf4 = (float4*)sf;
        for (int i = lane; i < N_ / 4; i += 32) { float4 v = f4[i]; sf4[i] = v; D4[i] = v; }
        ushort2* sp2 = (ushort2*)spar;
        for (int i = lane; i < N_ / 2; i += 32)
            sp2[i] = make_ushort2((unsigned short)(2 * i), (unsigned short)(2 * i + 1));
    }
    __syncwarp();
    int m = g_mcnt[k];
    const unsigned long long* mk = g_mk + (size_t)k * MS;
    for (int base = 0; base < m; base += 32) {
        int i = base + lane;
        bool valid = (i < m);
        int ru = -1, rv = -2;
        float fu = 0.f, fv = 0.f, kf = 0.f;
        if (valid) {
            unsigned long long kv = mk[i];
            unsigned e = (unsigned)kv;
            unsigned ob = (unsigned)(kv >> 32);
            unsigned fb2 = (ob & 0x80000000u) ? (ob & 0x7FFFFFFFu) : ~ob;
            kf = __uint_as_float(fb2);
            int u = ei[e], v = ei[E_ + e];
            int x = u;
            for (;;) { int p = spar[x]; if (p == x) break; int g2 = spar[p]; spar[x] = (unsigned short)g2; x = g2; }
            ru = x; fu = sf[x];
            x = v;
            for (;;) { int p = spar[x]; if (p == x) break; int g2 = spar[p]; spar[x] = (unsigned short)g2; x = g2; }
            rv = x; fv = sf[x];
        }
        __syncwarp();
        int lim = min(32, m - base);
        for (int t = 0; t < lim; t++) {
            int   bru = __shfl_sync(0xFFFFFFFFu, ru, t);
            int   brv = __shfl_sync(0xFFFFFFFFu, rv, t);
            float bfu = __shfl_sync(0xFFFFFFFFu, fu, t);
            float bfv = __shfl_sync(0xFFFFFFFFu, fv, t);
            float bkf = __shfl_sync(0xFFFFFFFFu, kf, t);
            if (bru != brv) {
                int older   = (bfu <= bfv) ? bru : brv;
                int younger = bru + brv - older;
                float folder = (bfu <= bfv) ? bfu : bfv;
                if (lane == (t & 31)) {
                    spar[younger] = (unsigned short)older;
                    D[younger] = bkf;
                }
                if (ru == younger) { ru = older; fu = folder; }
                if (rv == younger) { rv = older; fv = folder; }
            }
        }
        __syncwarp();
    }
}

// ---------------- coordinate activations ----------------
__global__ void k_act(const float* __restrict__ tri_t, const float* __restrict__ mu,
                      const float* __restrict__ sig, const float* __restrict__ lw,
                      const float* __restrict__ rc, const float* __restrict__ rr) {
    int i = blockIdx.x * blockDim.x + threadIdx.x;
    if (i >= N_ * KF) return;
    int v = i / KF, k = i - v * KF;
    float b = g_f[k * N_ + v], d = g_D[k * N_ + v];
    float s = sig[0];
    float inv = 1.f / (2.f * s * s);
    float r = fabsf(rr[0]);
    float o[12];
#pragma unroll
    for (int j = 0; j < 3; j++) o[j] = fmaxf(0.f, d - fabsf(tri_t[j] - b));
#pragma unroll
    for (int j = 0; j < 3; j++) {
        float dx = b - mu[2 * j], dy = d - mu[2 * j + 1];
        o[3 + j] = expf(-(dx * dx + dy * dy) * inv);
    }
#pragma unroll
    for (int j = 0; j < 3; j++) o[6 + j] = b * lw[2 * j] + d * lw[2 * j + 1];
#pragma unroll
    for (int j = 0; j < 3; j++) {
        float q = fabsf(b - rc[2 * j]) + fabsf(d - rc[2 * j + 1]);
        o[9 + j] = 1.f / (1.f + q) - 1.f / (1.f + fabsf(r - q));
    }
    float* dst = g_coord + (size_t)v * 96 + k * 12;
#pragma unroll
    for (int j = 0; j < 12; j++) dst[j] = o[j];
}

// ---------------- GEMM part 1: out = x @ Wx^T + bias ----------------
__global__ __launch_bounds__(256, 2) void k_gemm_x(const float* __restrict__ x,
                                                   const float* __restrict__ W,
                                                   const float* __restrict__ bias,
                                                   float* __restrict__ out) {
    __shared__ float As[16][136];
    __shared__ float Ws[16][136];
    int tid = threadIdx.x;
    int tx = tid & 15, ty = tid >> 4;
    int row0 = blockIdx.x * 128;
    int col0 = blockIdx.y * 128;
    unsigned long long acc[4][8];
#pragma unroll
    for (int p2 = 0; p2 < 4; p2++)
#pragma unroll
        for (int j = 0; j < 8; j++) acc[p2][j] = 0ull;

    for (int kt = 0; kt < 64; kt++) {
        int k0 = kt * 16;
#pragma unroll
        for (int l = 0; l < 2; l++) {
            int idx = tid + l * 256;
            int r = idx >> 2, c4 = idx & 3;
            int grow = row0 + r;
            float4 vv = make_float4(0.f, 0.f, 0.f, 0.f);
            if (grow < N_) vv = *(const float4*)(x + (size_t)grow * FIN + (k0 + c4 * 4));
            As[c4 * 4 + 0][r] = vv.x; As[c4 * 4 + 1][r] = vv.y;
            As[c4 * 4 + 2][r] = vv.z; As[c4 * 4 + 3][r] = vv.w;
        }
#pragma unroll
        for (int l = 0; l < 2; l++) {
            int idx = tid + l * 256;
            int r = idx >> 2, c4 = idx & 3;
            float4 vv = *(const float4*)(W + (size_t)(col0 + r) * KTOT + (k0 + c4 * 4));
            Ws[c4 * 4 + 0][r] = vv.x; Ws[c4 * 4 + 1][r] = vv.y;
            Ws[c4 * 4 + 2][r] = vv.z; Ws[c4 * 4 + 3][r] = vv.w;
        }
        __syncthreads();
#pragma unroll
        for (int kk = 0; kk < 16; kk++) {
            const unsigned long long* a8 = (const unsigned long long*)(&As[kk][ty * 8]);
            unsigned long long ap0 = a8[0], ap1 = a8[1], ap2 = a8[2], ap3 = a8[3];
            float4 w0 = *(const float4*)&Ws[kk][tx * 8];
            float4 w1 = *(const float4*)&Ws[kk][tx * 8 + 4];
            unsigned long long wp[8];
            PK2(wp[0], w0.x, w0.x); PK2(wp[1], w0.y, w0.y);
            PK2(wp[2], w0.z, w0.z); PK2(wp[3], w0.w, w0.w);
            PK2(wp[4], w1.x, w1.x); PK2(wp[5], w1.y, w1.y);
            PK2(wp[6], w1.z, w1.z); PK2(wp[7], w1.w, w1.w);
#pragma unroll
            for (int j = 0; j < 8; j++) {
                FMA2(acc[0][j], ap0, wp[j]);
                FMA2(acc[1][j], ap1, wp[j]);
                FMA2(acc[2][j], ap2, wp[j]);
                FMA2(acc[3][j], ap3, wp[j]);
            }
        }
        __syncthreads();
    }

    float bs[8];
#pragma unroll
    for (int j = 0; j < 8; j++) bs[j] = bias[col0 + tx * 8 + j];
#pragma unroll
    for (int p2 = 0; p2 < 4; p2++) {
        float lo[8], hi[8];
#pragma unroll
        for (int j = 0; j < 8; j++) { UPK2(lo[j], hi[j], acc[p2][j]); }
        int r0 = row0 + ty * 8 + p2 * 2;
        if (r0 < N_) {
            float* o0 = out + (size_t)r0 * FOUT + col0 + tx * 8;
            *(float4*)o0 = make_float4(lo[0] + bs[0], lo[1] + bs[1], lo[2] + bs[2], lo[3] + bs[3]);
            *(float4*)(o0 + 4) = make_float4(lo[4] + bs[4], lo[5] + bs[5], lo[6] + bs[6], lo[7] + bs[7]);
        }
        if (r0 + 1 < N_) {
            float* o1 = out + (size_t)(r0 + 1) * FOUT + col0 + tx * 8;
            *(float4*)o1 = make_float4(hi[0] + bs[0], hi[1] + bs[1], hi[2] + bs[2], hi[3] + bs[3]);
            *(float4*)(o1 + 4) = make_float4(hi[4] + bs[4], hi[5] + bs[5], hi[6] + bs[6], hi[7] + bs[7]);
        }
    }
}

// ---------------- GEMM part 2: out += coord @ Wc^T ----------------
__global__ __launch_bounds__(256, 2) void k_gemm_c(const float* __restrict__ W,
                                                   float* __restrict__ out) {
    __shared__ float As[16][136];
    __shared__ float Ws[16][136];
    int tid = threadIdx.x;
    int tx = tid & 15, ty = tid >> 4;
    int row0 = blockIdx.x * 128;
    int col0 = blockIdx.y * 128;
    unsigned long long acc[4][8];
#pragma unroll
    for (int p2 = 0; p2 < 4; p2++)
#pragma unroll
        for (int j = 0; j < 8; j++) acc[p2][j] = 0ull;

    for (int kt = 0; kt < 6; kt++) {
        int k0 = kt * 16;
#pragma unroll
        for (int l = 0; l < 2; l++) {
            int idx = tid + l * 256;
            int r = idx >> 2, c4 = idx & 3;
            int grow = row0 + r;
            float4 vv = make_float4(0.f, 0.f, 0.f, 0.f);
            if (grow < N_) vv = *(const float4*)(g_coord + (size_t)grow * 96 + (k0 + c4 * 4));
            As[c4 * 4 + 0][r] = vv.x; As[c4 * 4 + 1][r] = vv.y;
            As[c4 * 4 + 2][r] = vv.z; As[c4 * 4 + 3][r] = vv.w;
        }
#pragma unroll
        for (int l = 0; l < 2; l++) {
            int idx = tid + l * 256;
            int r = idx >> 2, c4 = idx & 3;
            float4 vv = *(const float4*)(W + (size_t)(col0 + r) * KTOT + (1024 + k0 + c4 * 4));
            Ws[c4 * 4 + 0][r] = vv.x; Ws[c4 * 4 + 1][r] = vv.y;
            Ws[c4 * 4 + 2][r] = vv.z; Ws[c4 * 4 + 3][r] = vv.w;
        }
        __syncthreads();
#pragma unroll
        for (int kk = 0; kk < 16; kk++) {
            const unsigned long long* a8 = (const unsigned long long*)(&As[kk][ty * 8]);
            unsigned long long ap0 = a8[0], ap1 = a8[1], ap2 = a8[2], ap3 = a8[3];
            float4 w0 = *(const float4*)&Ws[kk][tx * 8];
            float4 w1 = *(const float4*)&Ws[kk][tx * 8 + 4];
            unsigned long long wp[8];
            PK2(wp[0], w0.x, w0.x); PK2(wp[1], w0.y, w0.y);
            PK2(wp[2], w0.z, w0.z); PK2(wp[3], w0.w, w0.w);
            PK2(wp[4], w1.x, w1.x); PK2(wp[5], w1.y, w1.y);
            PK2(wp[6], w1.z, w1.z); PK2(wp[7], w1.w, w1.w);
#pragma unroll
            for (int j = 0; j < 8; j++) {
                FMA2(acc[0][j], ap0, wp[j]);
                FMA2(acc[1][j], ap1, wp[j]);
                FMA2(acc[2][j], ap2, wp[j]);
                FMA2(acc[3][j], ap3, wp[j]);
            }
        }
        __syncthreads();
    }

#pragma unroll
    for (int p2 = 0; p2 < 4; p2++) {
        float lo[8], hi[8];
#pragma unroll
        for (int j = 0; j < 8; j++) { UPK2(lo[j], hi[j], acc[p2][j]); }
        int r0 = row0 + ty * 8 + p2 * 2;
        if (r0 < N_) {
            float* o0 = out + (size_t)r0 * FOUT + col0 + tx * 8;
            float4 a0 = *(float4*)o0, a1 = *(float4*)(o0 + 4);
            a0.x += lo[0]; a0.y += lo[1]; a0.z += lo[2]; a0.w += lo[3];
            a1.x += lo[4]; a1.y += lo[5]; a1.z += lo[6]; a1.w += lo[7];
            *(float4*)o0 = a0; *(float4*)(o0 + 4) = a1;
        }
        if (r0 + 1 < N_) {
            float* o1 = out + (size_t)(r0 + 1) * FOUT + col0 + tx * 8;
            float4 a0 = *(float4*)o1, a1 = *(float4*)(o1 + 4);
            a0.x += hi[0]; a0.y += hi[1]; a0.z += hi[2]; a0.w += hi[3];
            a1.x += hi[4]; a1.y += hi[5]; a1.z += hi[6]; a1.w += hi[7];
            *(float4*)o1 = a0; *(float4*)(o1 + 4) = a1;
        }
    }
}

// ---------------- launcher: fork x-GEMM into the k_uf idle window ----------------
extern "C" void kernel_launch(void* const* d_in, const int* in_sizes, int n_in,
                              void* d_out, int out_size) {
    const float* x   = (const float*)d_in[0];
    const int*   ei  = (const int*)d_in[1];
    const float* fw  = (const float*)d_in[2];
    const float* fb  = (const float*)d_in[3];
    const float* tri = (const float*)d_in[4];
    const float* mu  = (const float*)d_in[5];
    const float* sig = (const float*)d_in[6];
    const float* lw  = (const float*)d_in[7];
    const float* rc  = (const float*)d_in[8];
    const float* rr  = (const float*)d_in[9];
    const float* W   = (const float*)d_in[10];
    const float* ob  = (const float*)d_in[11];
    float* out = (float*)d_out;

    cudaStream_t s2;
    cudaStreamCreateWithFlags(&s2, cudaStreamNonBlocking);
    cudaEvent_t evFork, evX;
    cudaEventCreateWithFlags(&evFork, cudaEventDisableTiming);
    cudaEventCreateWithFlags(&evX, cudaEventDisableTiming);

    dim3 gg((N_ + 127) / 128, FOUT / 128);

    // topology pipeline (runs uncontended at full chip)
    k_init<<<(KF * MS + 255) / 256, 256>>>();
    k_fall<<<(N_ + 7) / 8, 256>>>(x, fw, fb);

    for (int r = 0; r < 15; r++) {
        kA_edge<<<KF * E_ / 256, 256>>>(ei, r);
        kB_hook<<<KF * N_ / 256, 256>>>(ei, r);
        kC_flat<<<(KF * N_ + 255) / 256, 256>>>(r);
    }

    k_sloc<<<KF * (MS / 2048), 1024>>>();
    for (unsigned K2 = 4096; K2 <= MS; K2 <<= 1) {
        for (unsigned j = K2 >> 1; j >= 2048; j >>= 1)
            k_sglob<<<(KF * (MS / 2) + 255) / 256, 256>>>(K2, j);
        k_smerge<<<KF * (MS / 2048), 1024>>>(K2);
    }

    // fork HERE: x-GEMM fills the ~140 idle SMs during k_uf (8 CTAs) + k_act
    cudaEventRecord(evFork, 0);
    cudaStreamWaitEvent(s2, evFork, 0);
    k_gemm_x<<<gg, 256, 0, s2>>>(x, W, ob, out);
    cudaEventRecord(evX, s2);

    cudaFuncSetAttribute(k_uf, cudaFuncAttributeMaxDynamicSharedMemorySize, 122880);
    k_uf<<<KF, 32, 120000>>>(ei);
    k_act<<<(N_ * KF + 255) / 256, 256>>>(tri, mu, sig, lw, rc, rr);

    // join: coord-GEMM needs both k_act (coord) and k_gemm_x (out initialized)
    cudaStreamWaitEvent(0, evX, 0);
    k_gemm_c<<<gg, 256>>>(W, out);
}

// round 14
// speedup vs baseline: 1.3899x; 1.0742x over previous
#include <cuda_runtime.h>

#define N_ 20000
#define E_ 100000
#define KF 8
#define FIN 1024
#define FOUT 512
#define KTOT 1120
#define MS 32768

// ---------------- device scratch (no allocations) ----------------
__device__ float               g_f[KF * N_];
__device__ int                 g_par[KF * N_];
__device__ int                 g_hk[KF * N_];
__device__ unsigned long long  g_best[KF * N_];
__device__ unsigned long long  g_feA[KF * E_];
__device__ unsigned long long  g_feB[KF * E_];
__device__ int                 g_fcnt[2][KF];
__device__ unsigned long long  g_mk[KF * MS];
__device__ int                 g_mcnt[KF];
__device__ float               g_D[KF * N_];
__device__ float               g_coord[(size_t)N_ * 96];

// ---------------- packed f32x2 helpers ----------------
#define FMA2(d, a, b) asm("fma.rn.f32x2 %0, %1, %2, %0;" : "+l"(d) : "l"(a), "l"(b))
#define PK2(d, x, y)  asm("mov.b64 %0, {%1, %2};" : "=l"(d) : "f"(x), "f"(y))
#define UPK2(x, y, d) asm("mov.b64 {%0, %1}, %2;" : "=f"(x), "=f"(y) : "l"(d))

// ---------------- init ----------------
__global__ void k_init() {
    int i = blockIdx.x * blockDim.x + threadIdx.x;
    if (i < KF * N_) { g_par[i] = i % N_; g_best[i] = ~0ull; }
    if (i < KF * MS) g_mk[i] = ~0ull;
    if (i < KF)      { g_mcnt[i] = 0; g_fcnt[0][i] = 0; g_fcnt[1][i] = 0; }
}

// ---------------- f_all ----------------
__global__ __launch_bounds__(256) void k_fall(const float* __restrict__ x,
                                              const float* __restrict__ fw,
                                              const float* __restrict__ fb) {
    __shared__ float ws[KF][FIN];
    int tid = threadIdx.x;
    for (int i = tid; i < KF * FIN; i += 256) ws[i >> 10][i & 1023] = fw[i];
    __syncthreads();
    int warp = tid >> 5, lane = tid & 31;
    int row = blockIdx.x * 8 + warp;
    if (row >= N_) return;
    const float4* xr = (const float4*)(x + (size_t)row * FIN);
    float acc[KF];
#pragma unroll
    for (int k = 0; k < KF; k++) acc[k] = 0.f;
    for (int i = lane; i < FIN / 4; i += 32) {
        float4 xv = xr[i];
        int c = i * 4;
#pragma unroll
        for (int k = 0; k < KF; k++)
            acc[k] += xv.x * ws[k][c] + xv.y * ws[k][c + 1] +
                      xv.z * ws[k][c + 2] + xv.w * ws[k][c + 3];
    }
#pragma unroll
    for (int k = 0; k < KF; k++)
#pragma unroll
        for (int o = 16; o; o >>= 1) acc[k] += __shfl_xor_sync(0xFFFFFFFFu, acc[k], o);
    if (lane == 0) {
#pragma unroll
        for (int k = 0; k < KF; k++) g_f[k * N_ + row] = acc[k] + fb[k];
    }
}

// ---------------- Boruvka A: round0 computes keys inline; best atomics + compaction ----------------
__global__ void kA_edge(const int* __restrict__ ei, int r) {
    int p = r & 1;
    int i = blockIdx.x * blockDim.x + threadIdx.x;
    int k = i / E_, j = i - k * E_;
    int lane = threadIdx.x & 31;
    bool keep = false;
    unsigned long long kv = 0;
    int lim = (r == 0) ? E_ : g_fcnt[p][k];
    if (j < lim) {
        int e, u, v;
        if (r == 0) {
            e = j; u = ei[e]; v = ei[E_ + e];
            float key = fmaxf(g_f[k * N_ + u], g_f[k * N_ + v]);
            unsigned b = __float_as_uint(key);
            b = (b & 0x80000000u) ? ~b : (b | 0x80000000u);
            kv = ((unsigned long long)b << 32) | (unsigned)e;
        } else {
            kv = p ? g_feB[i] : g_feA[i];
            e = (int)(unsigned)kv; u = ei[e]; v = ei[E_ + e];
        }
        int cu = g_par[k * N_ + u], cv = g_par[k * N_ + v];
        if (cu != cv) {
            atomicMin(&g_best[k * N_ + cu], kv);
            atomicMin(&g_best[k * N_ + cv], kv);
            keep = true;
        }
    }
    unsigned m = __ballot_sync(0xFFFFFFFFu, keep);
    if (!m) return;
    int leader = __ffs(m) - 1;
    int pos = 0;
    if (lane == leader) pos = atomicAdd(&g_fcnt[p ^ 1][k], __popc(m));
    pos = __shfl_sync(0xFFFFFFFFu, pos, leader);
    if (keep) {
        int my = pos + __popc(m & ((1u << lane) - 1));
        if (p) g_feA[k * E_ + my] = kv; else g_feB[k * E_ + my] = kv;
    }
}

// ---------------- Boruvka B: hook + warp-aggregated MSF append (dead-round exit) ----------------
__global__ void kB_hook(const int* __restrict__ ei, int r) {
    int i = blockIdx.x * blockDim.x + threadIdx.x;
    int k = i / N_, n = i - k * N_;
    if (r > 0 && g_fcnt[r & 1][k] == 0) return;
    int lane = threadIdx.x & 31;
    bool emit = false;
    unsigned long long bb = 0;
    if (g_par[i] == n) {
        bb = g_best[i];
        if (bb == ~0ull) {
            g_hk[i] = -1;
        } else {
            unsigned e = (unsigned)bb;
            int u = ei[e], v = ei[E_ + e];
            int cu = g_par[k * N_ + u], cv = g_par[k * N_ + v];
            int o = (cu == n) ? cv : cu;
            g_hk[i] = o;
            unsigned long long bb2 = g_best[k * N_ + o];
            bool recip = (bb2 == bb);
            emit = (!recip || n < o);
        }
    }
    unsigned m = __ballot_sync(0xFFFFFFFFu, emit);
    if (!m) return;
    int leader = __ffs(m) - 1;
    int pos = 0;
    if (lane == leader) pos = atomicAdd(&g_mcnt[k], __popc(m));
    pos = __shfl_sync(0xFFFFFFFFu, pos, leader);
    if (emit) {
        int my = pos + __popc(m & ((1u << lane) - 1));
        g_mk[(size_t)k * MS + my] = bb;
    }
}

// ---------------- Boruvka C: apply hooks + flatten + reset (dead-round exit) ----------------
__global__ void kC_flat(int r) {
    int p = r & 1;
    int i = blockIdx.x * blockDim.x + threadIdx.x;
    if (i >= KF * N_) return;
    int k = i / N_, n = i - k * N_;
    if (r > 0 && g_fcnt[p][k] == 0) return;
    int kb = k * N_;
    int x = n;
    for (;;) {
        int pp = g_par[kb + x];
        if (pp != x) { x = pp; continue; }
        int o = g_hk[kb + x];
        if (o < 0) break;
        if (g_hk[kb + o] == x && x < o) break;
        x = o;
    }
    g_par[i] = x;
    g_best[i] = ~0ull;
    if (n == 0) g_fcnt[p][k] = 0;
}

// ---------------- bitonic sort ----------------
__global__ __launch_bounds__(1024) void k_sloc() {
    __shared__ unsigned long long s[2048];
    unsigned blk = blockIdx.x;
    size_t base = (size_t)blk * 2048;
    unsigned lbase = (blk % (MS / 2048)) * 2048;
    s[threadIdx.x] = g_mk[base + threadIdx.x];
    s[threadIdx.x + 1024] = g_mk[base + threadIdx.x + 1024];
    __syncthreads();
    for (unsigned k2 = 2; k2 <= 2048; k2 <<= 1) {
        for (unsigned j = k2 >> 1; j > 0; j >>= 1) {
            unsigned t = threadIdx.x;
            unsigned i = 2 * t - (t & (j - 1));
            bool up = (((lbase + i) & k2) == 0);
            unsigned long long a = s[i], b = s[i + j];
            if (up ? (a > b) : (a < b)) { s[i] = b; s[i + j] = a; }
            __syncthreads();
        }
    }
    g_mk[base + threadIdx.x] = s[threadIdx.x];
    g_mk[base + threadIdx.x + 1024] = s[threadIdx.x + 1024];
}

__global__ void k_sglob(unsigned K2, unsigned j) {
    unsigned gid = blockIdx.x * blockDim.x + threadIdx.x;
    if (gid >= KF * (MS / 2)) return;
    unsigned filt = gid / (MS / 2), t = gid % (MS / 2);
    unsigned i = 2 * t - (t & (j - 1));
    unsigned l = i + j;
    unsigned long long* g = g_mk + (size_t)filt * MS;
    bool up = ((i & K2) == 0);
    unsigned long long a = g[i], b = g[l];
    if (up ? (a > b) : (a < b)) { g[i] = b; g[l] = a; }
}

__global__ __launch_bounds__(1024) void k_smerge(unsigned K2) {
    __shared__ unsigned long long s[2048];
    unsigned blk = blockIdx.x;
    size_t base = (size_t)blk * 2048;
    unsigned lbase = (blk % (MS / 2048)) * 2048;
    s[threadIdx.x] = g_mk[base + threadIdx.x];
    s[threadIdx.x + 1024] = g_mk[base + threadIdx.x + 1024];
    __syncthreads();
    for (unsigned j = 1024; j > 0; j >>= 1) {
        unsigned t = threadIdx.x;
        unsigned i = 2 * t - (t & (j - 1));
        bool up = (((lbase + i) & K2) == 0);
        unsigned long long a = s[i], b = s[i + j];
        if (up ? (a > b) : (a < b)) { s[i] = b; s[i + j] = a; }
        __syncthreads();
    }
    g_mk[base + threadIdx.x] = s[threadIdx.x];
    g_mk[base + threadIdx.x + 1024] = s[threadIdx.x + 1024];
}

// ---------------- elder-rule UF: warp-synchronous register-mirrored commit (R10 winner) ----------------
__global__ __launch_bounds__(32) void k_uf(const int* __restrict__ ei) {
    extern __shared__ char dyn[];
    float* sf = (float*)dyn;
    unsigned short* spar = (unsigned short*)(dyn + 80000);
    int k = blockIdx.x, lane = threadIdx.x;
    const float* f = g_f + (size_t)k * N_;
    float* D = g_D + (size_t)k * N_;
    {
        const float4* f4 = (const float4*)f;
        float4* D4 = (float4*)D;
        float4* sf4 = (float4*)sf;
        for (int i = lane; i < N_ / 4; i += 32) { float4 v = f4[i]; sf4[i] = v; D4[i] = v; }
        ushort2* sp2 = (ushort2*)spar;
        for (int i = lane; i < N_ / 2; i += 32)
            sp2[i] = make_ushort2((unsigned short)(2 * i), (unsigned short)(2 * i + 1));
    }
    __syncwarp();
    int m = g_mcnt[k];
    const unsigned long long* mk = g_mk + (size_t)k * MS;
    for (int base = 0; base < m; base += 32) {
        int i = base + lane;
        bool valid = (i < m);
        int ru = -1, rv = -2;
        float fu = 0.f, fv = 0.f, kf = 0.f;
        if (valid) {
            unsigned long long kv = mk[i];
            unsigned e = (unsigned)kv;
            unsigned ob = (unsigned)(kv >> 32);
            unsigned fb2 = (ob & 0x80000000u) ? (ob & 0x7FFFFFFFu) : ~ob;
            kf = __uint_as_float(fb2);
            int u = ei[e], v = ei[E_ + e];
            int x = u;
            for (;;) { int p = spar[x]; if (p == x) break; int g2 = spar[p]; spar[x] = (unsigned short)g2; x = g2; }
            ru = x; fu = sf[x];
            x = v;
            for (;;) { int p = spar[x]; if (p == x) break; int g2 = spar[p]; spar[x] = (unsigned short)g2; x = g2; }
            rv = x; fv = sf[x];
        }
        __syncwarp();
        int lim = min(32, m - base);
        for (int t = 0; t < lim; t++) {
            int   bru = __shfl_sync(0xFFFFFFFFu, ru, t);
            int   brv = __shfl_sync(0xFFFFFFFFu, rv, t);
            float bfu = __shfl_sync(0xFFFFFFFFu, fu, t);
            float bfv = __shfl_sync(0xFFFFFFFFu, fv, t);
            float bkf = __shfl_sync(0xFFFFFFFFu, kf, t);
            if (bru != brv) {
                int older   = (bfu <= bfv) ? bru : brv;
                int younger = bru + brv - older;
                float folder = (bfu <= bfv) ? bfu : bfv;
                if (lane == (t & 31)) {
                    spar[younger] = (unsigned short)older;
                    D[younger] = bkf;
                }
                if (ru == younger) { ru = older; fu = folder; }
                if (rv == younger) { rv = older; fv = folder; }
            }
        }
        __syncwarp();
    }
}

// ---------------- coordinate activations ----------------
__global__ void k_act(const float* __restrict__ tri_t, const float* __restrict__ mu,
                      const float* __restrict__ sig, const float* __restrict__ lw,
                      const float* __restrict__ rc, const float* __restrict__ rr) {
    int i = blockIdx.x * blockDim.x + threadIdx.x;
    if (i >= N_ * KF) return;
    int v = i / KF, k = i - v * KF;
    float b = g_f[k * N_ + v], d = g_D[k * N_ + v];
    float s = sig[0];
    float inv = 1.f / (2.f * s * s);
    float r = fabsf(rr[0]);
    float o[12];
#pragma unroll
    for (int j = 0; j < 3; j++) o[j] = fmaxf(0.f, d - fabsf(tri_t[j] - b));
#pragma unroll
    for (int j = 0; j < 3; j++) {
        float dx = b - mu[2 * j], dy = d - mu[2 * j + 1];
        o[3 + j] = expf(-(dx * dx + dy * dy) * inv);
    }
#pragma unroll
    for (int j = 0; j < 3; j++) o[6 + j] = b * lw[2 * j] + d * lw[2 * j + 1];
#pragma unroll
    for (int j = 0; j < 3; j++) {
        float q = fabsf(b - rc[2 * j]) + fabsf(d - rc[2 * j + 1]);
        o[9 + j] = 1.f / (1.f + q) - 1.f / (1.f + fabsf(r - q));
    }
    float* dst = g_coord + (size_t)v * 96 + k * 12;
#pragma unroll
    for (int j = 0; j < 12; j++) dst[j] = o[j];
}

// ---------------- GEMM part 1: out = x @ Wx^T + bias ----------------
__global__ __launch_bounds__(256, 2) void k_gemm_x(const float* __restrict__ x,
                                                   const float* __restrict__ W,
                                                   const float* __restrict__ bias,
                                                   float* __restrict__ out) {
    __shared__ float As[16][136];
    __shared__ float Ws[16][136];
    int tid = threadIdx.x;
    int tx = tid & 15, ty = tid >> 4;
    int row0 = blockIdx.x * 128;
    int col0 = blockIdx.y * 128;
    unsigned long long acc[4][8];
#pragma unroll
    for (int p2 = 0; p2 < 4; p2++)
#pragma unroll
        for (int j = 0; j < 8; j++) acc[p2][j] = 0ull;

    for (int kt = 0; kt < 64; kt++) {
        int k0 = kt * 16;
#pragma unroll
        for (int l = 0; l < 2; l++) {
            int idx = tid + l * 256;
            int r = idx >> 2, c4 = idx & 3;
            int grow = row0 + r;
            float4 vv = make_float4(0.f, 0.f, 0.f, 0.f);
            if (grow < N_) vv = *(const float4*)(x + (size_t)grow * FIN + (k0 + c4 * 4));
            As[c4 * 4 + 0][r] = vv.x; As[c4 * 4 + 1][r] = vv.y;
            As[c4 * 4 + 2][r] = vv.z; As[c4 * 4 + 3][r] = vv.w;
        }
#pragma unroll
        for (int l = 0; l < 2; l++) {
            int idx = tid + l * 256;
            int r = idx >> 2, c4 = idx & 3;
            float4 vv = *(const float4*)(W + (size_t)(col0 + r) * KTOT + (k0 + c4 * 4));
            Ws[c4 * 4 + 0][r] = vv.x; Ws[c4 * 4 + 1][r] = vv.y;
            Ws[c4 * 4 + 2][r] = vv.z; Ws[c4 * 4 + 3][r] = vv.w;
        }
        __syncthreads();
#pragma unroll
        for (int kk = 0; kk < 16; kk++) {
            const unsigned long long* a8 = (const unsigned long long*)(&As[kk][ty * 8]);
            unsigned long long ap0 = a8[0], ap1 = a8[1], ap2 = a8[2], ap3 = a8[3];
            float4 w0 = *(const float4*)&Ws[kk][tx * 8];
            float4 w1 = *(const float4*)&Ws[kk][tx * 8 + 4];
            unsigned long long wp[8];
            PK2(wp[0], w0.x, w0.x); PK2(wp[1], w0.y, w0.y);
            PK2(wp[2], w0.z, w0.z); PK2(wp[3], w0.w, w0.w);
            PK2(wp[4], w1.x, w1.x); PK2(wp[5], w1.y, w1.y);
            PK2(wp[6], w1.z, w1.z); PK2(wp[7], w1.w, w1.w);
#pragma unroll
            for (int j = 0; j < 8; j++) {
                FMA2(acc[0][j], ap0, wp[j]);
                FMA2(acc[1][j], ap1, wp[j]);
                FMA2(acc[2][j], ap2, wp[j]);
                FMA2(acc[3][j], ap3, wp[j]);
            }
        }
        __syncthreads();
    }

    float bs[8];
#pragma unroll
    for (int j = 0; j < 8; j++) bs[j] = bias[col0 + tx * 8 + j];
#pragma unroll
    for (int p2 = 0; p2 < 4; p2++) {
        float lo[8], hi[8];
#pragma unroll
        for (int j = 0; j < 8; j++) { UPK2(lo[j], hi[j], acc[p2][j]); }
        int r0 = row0 + ty * 8 + p2 * 2;
        if (r0 < N_) {
            float* o0 = out + (size_t)r0 * FOUT + col0 + tx * 8;
            *(float4*)o0 = make_float4(lo[0] + bs[0], lo[1] + bs[1], lo[2] + bs[2], lo[3] + bs[3]);
            *(float4*)(o0 + 4) = make_float4(lo[4] + bs[4], lo[5] + bs[5], lo[6] + bs[6], lo[7] + bs[7]);
        }
        if (r0 + 1 < N_) {
            float* o1 = out + (size_t)(r0 + 1) * FOUT + col0 + tx * 8;
            *(float4*)o1 = make_float4(hi[0] + bs[0], hi[1] + bs[1], hi[2] + bs[2], hi[3] + bs[3]);
            *(float4*)(o1 + 4) = make_float4(hi[4] + bs[4], hi[5] + bs[5], hi[6] + bs[6], hi[7] + bs[7]);
        }
    }
}

// ---------------- GEMM part 2: out += coord @ Wc^T ----------------
__global__ __launch_bounds__(256, 2) void k_gemm_c(const float* __restrict__ W,
                                                   float* __restrict__ out) {
    __shared__ float As[16][136];
    __shared__ float Ws[16][136];
    int tid = threadIdx.x;
    int tx = tid & 15, ty = tid >> 4;
    int row0 = blockIdx.x * 128;
    int col0 = blockIdx.y * 128;
    unsigned long long acc[4][8];
#pragma unroll
    for (int p2 = 0; p2 < 4; p2++)
#pragma unroll
        for (int j = 0; j < 8; j++) acc[p2][j] = 0ull;

    for (int kt = 0; kt < 6; kt++) {
        int k0 = kt * 16;
#pragma unroll
        for (int l = 0; l < 2; l++) {
            int idx = tid + l * 256;
            int r = idx >> 2, c4 = idx & 3;
            int grow = row0 + r;
            float4 vv = make_float4(0.f, 0.f, 0.f, 0.f);
            if (grow < N_) vv = *(const float4*)(g_coord + (size_t)grow * 96 + (k0 + c4 * 4));
            As[c4 * 4 + 0][r] = vv.x; As[c4 * 4 + 1][r] = vv.y;
            As[c4 * 4 + 2][r] = vv.z; As[c4 * 4 + 3][r] = vv.w;
        }
#pragma unroll
        for (int l = 0; l < 2; l++) {
            int idx = tid + l * 256;
            int r = idx >> 2, c4 = idx & 3;
            float4 vv = *(const float4*)(W + (size_t)(col0 + r) * KTOT + (1024 + k0 + c4 * 4));
            Ws[c4 * 4 + 0][r] = vv.x; Ws[c4 * 4 + 1][r] = vv.y;
            Ws[c4 * 4 + 2][r] = vv.z; Ws[c4 * 4 + 3][r] = vv.w;
        }
        __syncthreads();
#pragma unroll
        for (int kk = 0; kk < 16; kk++) {
            const unsigned long long* a8 = (const unsigned long long*)(&As[kk][ty * 8]);
            unsigned long long ap0 = a8[0], ap1 = a8[1], ap2 = a8[2], ap3 = a8[3];
            float4 w0 = *(const float4*)&Ws[kk][tx * 8];
            float4 w1 = *(const float4*)&Ws[kk][tx * 8 + 4];
            unsigned long long wp[8];
            PK2(wp[0], w0.x, w0.x); PK2(wp[1], w0.y, w0.y);
            PK2(wp[2], w0.z, w0.z); PK2(wp[3], w0.w, w0.w);
            PK2(wp[4], w1.x, w1.x); PK2(wp[5], w1.y, w1.y);
            PK2(wp[6], w1.z, w1.z); PK2(wp[7], w1.w, w1.w);
#pragma unroll
            for (int j = 0; j < 8; j++) {
                FMA2(acc[0][j], ap0, wp[j]);
                FMA2(acc[1][j], ap1, wp[j]);
                FMA2(acc[2][j], ap2, wp[j]);
                FMA2(acc[3][j], ap3, wp[j]);
            }
        }
        __syncthreads();
    }

#pragma unroll
    for (int p2 = 0; p2 < 4; p2++) {
        float lo[8], hi[8];
#pragma unroll
        for (int j = 0; j < 8; j++) { UPK2(lo[j], hi[j], acc[p2][j]); }
        int r0 = row0 + ty * 8 + p2 * 2;
        if (r0 < N_) {
            float* o0 = out + (size_t)r0 * FOUT + col0 + tx * 8;
            float4 a0 = *(float4*)o0, a1 = *(float4*)(o0 + 4);
            a0.x += lo[0]; a0.y += lo[1]; a0.z += lo[2]; a0.w += lo[3];
            a1.x += lo[4]; a1.y += lo[5]; a1.z += lo[6]; a1.w += lo[7];
            *(float4*)o0 = a0; *(float4*)(o0 + 4) = a1;
        }
        if (r0 + 1 < N_) {
            float* o1 = out + (size_t)(r0 + 1) * FOUT + col0 + tx * 8;
            float4 a0 = *(float4*)o1, a1 = *(float4*)(o1 + 4);
            a0.x += hi[0]; a0.y += hi[1]; a0.z += hi[2]; a0.w += hi[3];
            a1.x += hi[4]; a1.y += hi[5]; a1.z += hi[6]; a1.w += hi[7];
            *(float4*)o1 = a0; *(float4*)(o1 + 4) = a1;
        }
    }
}

// ---------------- launcher: topology on HIGH-priority forked stream; x-GEMM on
//                  the default (lowest-priority) stream soaks idle SMs ----------------
extern "C" void kernel_launch(void* const* d_in, const int* in_sizes, int n_in,
                              void* d_out, int out_size) {
    const float* x   = (const float*)d_in[0];
    const int*   ei  = (const int*)d_in[1];
    const float* fw  = (const float*)d_in[2];
    const float* fb  = (const float*)d_in[3];
    const float* tri = (const float*)d_in[4];
    const float* mu  = (const float*)d_in[5];
    const float* sig = (const float*)d_in[6];
    const float* lw  = (const float*)d_in[7];
    const float* rc  = (const float*)d_in[8];
    const float* rr  = (const float*)d_in[9];
    const float* W   = (const float*)d_in[10];
    const float* ob  = (const float*)d_in[11];
    float* out = (float*)d_out;

    int loPri = 0, hiPri = 0;
    cudaDeviceGetStreamPriorityRange(&loPri, &hiPri);
    cudaStream_t s1;                          // high-priority topology stream
    cudaStreamCreateWithPriority(&s1, cudaStreamNonBlocking, hiPri);
    cudaEvent_t evRoot, evT;
    cudaEventCreateWithFlags(&evRoot, cudaEventDisableTiming);
    cudaEventCreateWithFlags(&evT, cudaEventDisableTiming);

    dim3 gg((N_ + 127) / 128, FOUT / 128);

    // fork: topology chain moves to the high-priority stream
    cudaEventRecord(evRoot, 0);
    cudaStreamWaitEvent(s1, evRoot, 0);

    // x-GEMM stays on the default (priority-0 = lowest) stream: fills idle SMs
    k_gemm_x<<<gg, 256>>>(x, W, ob, out);

    // topology pipeline on s1 (always preferred for CTA slots)
    k_init<<<(KF * MS + 255) / 256, 256, 0, s1>>>();
    k_fall<<<(N_ + 7) / 8, 256, 0, s1>>>(x, fw, fb);

    for (int r = 0; r < 15; r++) {
        kA_edge<<<KF * E_ / 256, 256, 0, s1>>>(ei, r);
        kB_hook<<<KF * N_ / 256, 256, 0, s1>>>(ei, r);
        kC_flat<<<(KF * N_ + 255) / 256, 256, 0, s1>>>(r);
    }

    k_sloc<<<KF * (MS / 2048), 1024, 0, s1>>>();
    for (unsigned K2 = 4096; K2 <= MS; K2 <<= 1) {
        for (unsigned j = K2 >> 1; j >= 2048; j >>= 1)
            k_sglob<<<(KF * (MS / 2) + 255) / 256, 256, 0, s1>>>(K2, j);
        k_smerge<<<KF * (MS / 2048), 1024, 0, s1>>>(K2);
    }

    cudaFuncSetAttribute(k_uf, cudaFuncAttributeMaxDynamicSharedMemorySize, 122880);
    k_uf<<<KF, 32, 120000, s1>>>(ei);
    k_act<<<(N_ * KF + 255) / 256, 256, 0, s1>>>(tri, mu, sig, lw, rc, rr);
    cudaEventRecord(evT, s1);

    // join on default stream: gemm_c needs k_act (coord) and k_gemm_x (out init)
    cudaStreamWaitEvent(0, evT, 0);
    k_gemm_c<<<gg, 256>>>(W, out);
}